// round 2
// baseline (speedup 1.0000x reference)
#include <cuda_runtime.h>
#include <stdint.h>

#define NB    8
#define NMEL  80
#define NT    512
#define NF    401
#define NFFT  800
#define LOUT  102200
#define LPAD  103000
#define ROWS  4096
#define K2    802
#define NTOT  1642496     /* ROWS*NF  */
#define FRTOT 3276800     /* ROWS*NFFT */

// ------------------------- device scratch (no allocs) ------------------------
__device__ float g_fb  [NF*NMEL];
__device__ float g_fbT [NMEL*NF];
__device__ float g_win [NFFT];
__device__ float g_wsqi[LPAD];
__device__ float g_Bi  [K2*NFFT];   // irfft DFT matrix [k][n], win & 1/800 & weights folded
__device__ float g_Bs  [NFFT*K2];   // rfft DFT matrix  [n][k], win folded
__device__ float g_spec[NTOT];
__device__ float g_vel [NTOT];
__device__ float g_diff[ROWS*NMEL];
__device__ float g_mag [NTOT];
__device__ float g_angR[NTOT];
__device__ float g_angI[NTOT];
__device__ float g_tR  [NTOT];
__device__ float g_tI  [NTOT];
__device__ float g_P   [ROWS*K2];
__device__ float g_fr  [FRTOT];
__device__ float g_reb [ROWS*K2];
__device__ float g_inv [NB*LOUT];
__device__ float g_peak[NB];

// ------------------------- threefry-2x32 (JAX schedule) ----------------------
__host__ __device__ inline void tf_block(unsigned k0, unsigned k1,
                                         unsigned c0, unsigned c1,
                                         unsigned &o0, unsigned &o1){
  unsigned ks2 = k0 ^ k1 ^ 0x1BD11BDAu;
  unsigned x0 = c0 + k0, x1 = c1 + k1;
#define TFR(r) { x0 += x1; x1 = (x1 << (r)) | (x1 >> (32 - (r))); x1 ^= x0; }
  TFR(13) TFR(15) TFR(26) TFR(6)  x0 += k1;  x1 += ks2 + 1u;
  TFR(17) TFR(29) TFR(16) TFR(24) x0 += ks2; x1 += k0 + 2u;
  TFR(13) TFR(15) TFR(26) TFR(6)  x0 += k0;  x1 += k1 + 3u;
  TFR(17) TFR(29) TFR(16) TFR(24) x0 += k1;  x1 += ks2 + 4u;
  TFR(13) TFR(15) TFR(26) TFR(6)  x0 += ks2; x1 += k0 + 5u;
#undef TFR
  o0 = x0; o1 = x1;
}

__device__ __forceinline__ float u01(unsigned bits){
  return __uint_as_float((bits >> 9) | 0x3f800000u) - 1.0f;
}

// ------------------------- setup kernels ------------------------------------
__global__ void k_setup1(){
  int i = blockIdx.x*blockDim.x + threadIdx.x;
  if (i < NFFT) g_win[i] = (float)(0.5 - 0.5*cospi((double)i/400.0));
  if (i < NF*NMEL){
    int f = i / NMEL, m = i - f*NMEL;
    double freq = 10.0 * f;
    double mmax = 2595.0 * log10(1.0 + 4000.0/700.0);
    double p0 = 700.0*(pow(10.0, (mmax*(double)(m  )/81.0)/2595.0) - 1.0);
    double p1 = 700.0*(pow(10.0, (mmax*(double)(m+1)/81.0)/2595.0) - 1.0);
    double p2 = 700.0*(pow(10.0, (mmax*(double)(m+2)/81.0)/2595.0) - 1.0);
    double down = (freq - p0) / (p1 - p0);
    double up   = (p2 - freq) / (p2 - p1);
    double v = fmax(0.0, fmin(down, up));
    g_fb [f*NMEL + m] = (float)v;
    g_fbT[m*NF  + f] = (float)v;
  }
}

__global__ void k_setup2(){
  int i = blockIdx.x*blockDim.x + threadIdx.x;
  if (i < LPAD){
    int j = i;
    int tlo = (j >= 600) ? (j-600)/200 : 0;
    int thi = j/200; if (thi > 511) thi = 511;
    double s = 0.0;
    for (int t = tlo; t <= thi; t++){
      double w = (double)g_win[j - 200*t];
      s += w*w;
    }
    s = fmax(s, 1e-11);
    g_wsqi[j] = (float)(1.0 / s);
  }
  int ib = i - LPAD;
  if (ib >= 0 && ib < K2*NFFT){
    int k = ib / NFFT, n = ib - k*NFFT;
    double v;
    if (k < NF){
      double w = (k == 0 || k == 400) ? 1.0 : 2.0;
      int r = (k*n) % 800;
      v = (w/800.0) * cospi((double)r/400.0);
    } else {
      int kk = k - NF;
      double w = (kk == 0 || kk == 400) ? 1.0 : 2.0;
      int r = (kk*n) % 800;
      v = -(w/800.0) * sinpi((double)r/400.0);
    }
    g_Bi[ib] = (float)(v * (double)g_win[n]);
  }
  int is = i - LPAD - K2*NFFT;
  if (is >= 0 && is < NFFT*K2){
    int n = is / K2, k = is - n*K2;
    double v;
    if (k < NF){
      int r = (k*n) % 800;
      v = cospi((double)r/400.0);
    } else {
      int kk = k - NF;
      int r = (kk*n) % 800;
      v = -sinpi((double)r/400.0);
    }
    g_Bs[is] = (float)(v * (double)g_win[n]);
  }
}

// ------------------------- RNG init ------------------------------------------
__global__ void k_init(unsigned a0, unsigned a1, unsigned r0, unsigned r1,
                       unsigned q0, unsigned q1){
  int i = blockIdx.x*blockDim.x + threadIdx.x;
  if (i >= NTOT) return;
  unsigned o0, o1;
  tf_block(a0, a1, 0u, (unsigned)i, o0, o1);
  g_spec[i] = u01(o0 ^ o1);                     // spec0 is (B,T,F) = our layout
  g_vel[i] = 0.f; g_tR[i] = 0.f; g_tI[i] = 0.f;
  // angles drawn in (B,F,T) order -> remap flat index
  int b = i / (NT*NF);
  int rem = i - b*(NT*NF);
  int t = rem / NF, f = rem - t*NF;
  unsigned j = (unsigned)(b*(NF*NT) + f*NT + t);
  tf_block(r0, r1, 0u, j, o0, o1); g_angR[i] = u01(o0 ^ o1);
  tf_block(q0, q1, 0u, j, o0, o1); g_angI[i] = u01(o0 ^ o1);
}

// ------------------------- 64x64 SGEMM (inverse-mel, fused epilogues) --------
// EPI 1: C = mel_t - A@B (diff).  EPI 2: momentum update of vel/spec.
template<int EPI>
__global__ __launch_bounds__(256)
void sgemm64(const float* __restrict__ A, const float* __restrict__ Bm,
             float* __restrict__ C, int N, int K, const float* __restrict__ X){
  __shared__ float As[16][64];
  __shared__ float Bs[16][64];
  const int tid = threadIdx.x;
  const int tx = tid & 15, ty = tid >> 4;
  const int bm = blockIdx.y << 6, bn = blockIdx.x << 6;
  float acc[4][4] = {};
  for (int k0 = 0; k0 < K; k0 += 16){
#pragma unroll
    for (int i = 0; i < 4; i++){
      int lin = (tid << 2) + i;
      int m = lin >> 4, kk = lin & 15;
      As[kk][m] = (k0 + kk < K) ? A[(bm + m)*K + k0 + kk] : 0.f;
    }
#pragma unroll
    for (int i = 0; i < 4; i++){
      int lin = tid + (i << 8);
      int kk = lin >> 6, nn = lin & 63;
      Bs[kk][nn] = (k0 + kk < K && bn + nn < N) ? Bm[(k0 + kk)*N + bn + nn] : 0.f;
    }
    __syncthreads();
#pragma unroll
    for (int kk = 0; kk < 16; kk++){
      float a[4], b[4];
#pragma unroll
      for (int i = 0; i < 4; i++) a[i] = As[kk][(ty << 2) + i];
#pragma unroll
      for (int j = 0; j < 4; j++) b[j] = Bs[kk][(tx << 2) + j];
#pragma unroll
      for (int i = 0; i < 4; i++)
#pragma unroll
        for (int j = 0; j < 4; j++) acc[i][j] = fmaf(a[i], b[j], acc[i][j]);
    }
    __syncthreads();
  }
#pragma unroll
  for (int i = 0; i < 4; i++){
    int row = bm + (ty << 2) + i;
#pragma unroll
    for (int j = 0; j < 4; j++){
      int col = bn + (tx << 2) + j;
      if (col >= N) continue;
      int idx = row*N + col;
      if (EPI == 1){
        int b = row >> 9, t = row & 511;
        C[idx] = X[(b*NMEL + col)*NT + t] - acc[i][j];     // mel_t - spec@fb
      } else {
        float g = -0.003125f * acc[i][j];                  // -2/(B*M) * diff@fb^T
        float v = 0.9f * g_vel[idx] + g;
        g_vel[idx] = v;
        float s = C[idx] - 0.1f * v;
        C[idx] = fmaxf(s, 0.f);
      }
    }
  }
}

// ------------------------- 128x128 SGEMM (DFT matmuls), M = 4096 -------------
__global__ __launch_bounds__(256)
void sgemm_big(const float* __restrict__ A, const float* __restrict__ B,
               float* __restrict__ C, int N, int K){
  __shared__ float As[16][128];
  __shared__ float Bs[16][128];
  const int tid = threadIdx.x;
  const int tx = tid & 15, ty = tid >> 4;
  const int bm = blockIdx.y << 7, bn = blockIdx.x << 7;
  float acc[8][8];
#pragma unroll
  for (int i = 0; i < 8; i++)
#pragma unroll
    for (int j = 0; j < 8; j++) acc[i][j] = 0.f;
  for (int k0 = 0; k0 < K; k0 += 16){
#pragma unroll
    for (int i = 0; i < 8; i++){
      int lin = (tid << 3) + i;
      int m = lin >> 4, kk = lin & 15;
      As[kk][m] = (k0 + kk < K) ? A[(bm + m)*K + k0 + kk] : 0.f;
    }
#pragma unroll
    for (int i = 0; i < 8; i++){
      int lin = tid + (i << 8);
      int kk = lin >> 7, nn = lin & 127;
      Bs[kk][nn] = (k0 + kk < K && bn + nn < N) ? B[(k0 + kk)*N + bn + nn] : 0.f;
    }
    __syncthreads();
#pragma unroll
    for (int kk = 0; kk < 16; kk++){
      float a[8], b[8];
#pragma unroll
      for (int i = 0; i < 8; i++) a[i] = As[kk][(ty << 3) + i];
#pragma unroll
      for (int j = 0; j < 8; j++) b[j] = Bs[kk][(tx << 3) + j];
#pragma unroll
      for (int i = 0; i < 8; i++)
#pragma unroll
        for (int j = 0; j < 8; j++) acc[i][j] = fmaf(a[i], b[j], acc[i][j]);
    }
    __syncthreads();
  }
#pragma unroll
  for (int i = 0; i < 8; i++){
    int row = bm + (ty << 3) + i;
#pragma unroll
    for (int j = 0; j < 8; j++){
      int col = bn + (tx << 3) + j;
      if (col < N) C[row*N + col] = acc[i][j];
    }
  }
}

// ------------------------- elementwise kernels -------------------------------
__global__ void k_mag(){
  int i = blockIdx.x*blockDim.x + threadIdx.x;
  if (i < NTOT) g_mag[i] = sqrtf(g_spec[i]);
}

__global__ void k_pack(){
  int i = blockIdx.x*blockDim.x + threadIdx.x;
  if (i >= NTOT) return;
  int row = i / NF, f = i - row*NF;
  float m = g_mag[i];
  g_P[row*K2 + f]      = m * g_angR[i];
  g_P[row*K2 + NF + f] = m * g_angI[i];
}

__global__ void k_ola(){
  int i = blockIdx.x*blockDim.x + threadIdx.x;
  if (i >= NB*LOUT) return;
  int b = i / LOUT, l = i - b*LOUT;
  int j = l + 400;
  int tlo = (j >= 600) ? (j-600)/200 : 0;
  int thi = j/200; if (thi > 511) thi = 511;
  float s = 0.f;
  for (int t = tlo; t <= thi; t++)
    s += g_fr[(b*NT + t)*NFFT + (j - 200*t)];
  g_inv[i] = s * g_wsqi[j];
}

__global__ void k_gather(){
  int i = blockIdx.x*blockDim.x + threadIdx.x;
  if (i >= FRTOT) return;
  int row = i / NFFT, n = i - row*NFFT;
  int b = row >> 9, t = row & 511;
  int src = t*200 + n - 400;            // reflect pad of length-LOUT signal
  if (src < 0) src = -src;
  else if (src >= LOUT) src = 2*LOUT - 2 - src;
  g_fr[i] = g_inv[b*LOUT + src];
}

__global__ void k_update(){
  int i = blockIdx.x*blockDim.x + threadIdx.x;
  if (i >= NTOT) return;
  int row = i / NF, f = i - row*NF;
  float re = g_reb[row*K2 + f];
  float im = g_reb[row*K2 + NF + f];
  float nR = re - 0.49748743718592965f * g_tR[i];   // 0.99/1.99
  float nI = im - 0.49748743718592965f * g_tI[i];
  float d = sqrtf(nR*nR + nI*nI) + 1e-16f;
  g_angR[i] = nR / d;
  g_angI[i] = nI / d;
  g_tR[i] = re; g_tI[i] = im;
}

__global__ void k_peak(){
  __shared__ float sm[256];
  int b = blockIdx.x;
  float mx = 0.f;
  for (int l = threadIdx.x; l < LOUT; l += 256)
    mx = fmaxf(mx, fabsf(g_inv[b*LOUT + l]));
  sm[threadIdx.x] = mx;
  __syncthreads();
  for (int s = 128; s > 0; s >>= 1){
    if (threadIdx.x < s) sm[threadIdx.x] = fmaxf(sm[threadIdx.x], sm[threadIdx.x + s]);
    __syncthreads();
  }
  if (threadIdx.x == 0) g_peak[b] = 0.98855309465693896f / sm[0];  // 10^(-0.1/20)
}

__global__ void k_scale(float* __restrict__ out){
  int i = blockIdx.x*blockDim.x + threadIdx.x;
  if (i >= NB*LOUT) return;
  out[i] = g_inv[i] * g_peak[i / LOUT];
}

// ------------------------- host driver ---------------------------------------
extern "C" void kernel_launch(void* const* d_in, const int* in_sizes, int n_in,
                              void* d_out, int out_size){
  const float* x = (const float*)d_in[0];
  float* out = (float*)d_out;

  float *pSpec, *pDiff, *pFb, *pFbT, *pP, *pBi, *pBs, *pFr, *pReb;
  cudaGetSymbolAddress((void**)&pSpec, g_spec);
  cudaGetSymbolAddress((void**)&pDiff, g_diff);
  cudaGetSymbolAddress((void**)&pFb,   g_fb);
  cudaGetSymbolAddress((void**)&pFbT,  g_fbT);
  cudaGetSymbolAddress((void**)&pP,    g_P);
  cudaGetSymbolAddress((void**)&pBi,   g_Bi);
  cudaGetSymbolAddress((void**)&pBs,   g_Bs);
  cudaGetSymbolAddress((void**)&pFr,   g_fr);
  cudaGetSymbolAddress((void**)&pReb,  g_reb);

  // JAX key derivation: key(1)=(0,1); partitionable split -> child_i = block(key,(0,i))
  unsigned a0,a1,b0,b1,r0,r1,q0,q1;
  tf_block(0u,1u, 0u,0u, a0,a1);   // k1  (inverse mel spec0)
  tf_block(0u,1u, 0u,1u, b0,b1);   // k2  (griffin-lim)
  tf_block(b0,b1, 0u,0u, r0,r1);   // kr  (angle real)
  tf_block(b0,b1, 0u,1u, q0,q1);   // ki  (angle imag)

  k_setup1<<<(NF*NMEL + 255)/256, 256>>>();
  k_setup2<<<(LPAD + 2*K2*NFFT + 255)/256, 256>>>();
  k_init<<<(NTOT + 255)/256, 256>>>(a0,a1,r0,r1,q0,q1);

  // InverseMelScale: 50 SGD+momentum iterations
  for (int it = 0; it < 50; it++){
    sgemm64<1><<<dim3(2,64), 256>>>(pSpec, pFb,  pDiff, NMEL, NF,   x);
    sgemm64<2><<<dim3(7,64), 256>>>(pDiff, pFbT, pSpec, NF,   NMEL, (const float*)0);
  }

  k_mag<<<(NTOT + 255)/256, 256>>>();

  // Griffin-Lim: 30 iterations
  for (int it = 0; it < 30; it++){
    k_pack  <<<(NTOT + 255)/256, 256>>>();
    sgemm_big<<<dim3(7,32), 256>>>(pP,  pBi, pFr,  NFFT, K2);   // istft frames
    k_ola   <<<(NB*LOUT + 255)/256, 256>>>();
    k_gather<<<(FRTOT + 255)/256, 256>>>();
    sgemm_big<<<dim3(7,32), 256>>>(pFr, pBs, pReb, K2, NFFT);   // stft rebuild
    k_update<<<(NTOT + 255)/256, 256>>>();
  }

  // final istft with converged phases
  k_pack  <<<(NTOT + 255)/256, 256>>>();
  sgemm_big<<<dim3(7,32), 256>>>(pP, pBi, pFr, NFFT, K2);
  k_ola   <<<(NB*LOUT + 255)/256, 256>>>();

  // normalize to -0.1 dB peak
  k_peak <<<NB, 256>>>();
  k_scale<<<(NB*LOUT + 255)/256, 256>>>(out);
}